// round 16
// baseline (speedup 1.0000x reference)
#include <cuda_runtime.h>
#include <cuda_bf16.h>
#include <cstdint>
#include <math.h>

// ---------------- problem constants ----------------
#define T_TOK 512
#define HDIM 2880
#define IDIM 2880
#define TWO_I 5760
#define NEXP 8
#define KSEL 4
#define ALPHA 1.702f
#define LIMIT 7.0f

// ---------------- GEMM tiling ----------------
#define MT 128
#define NT 96
#define KC 32
#define NCHUNK (HDIM / KC)     // 90
#define ROWSTR 40              // smem row stride (32 data + 8 pad) bf16 elems

#define SA_EL (MT * ROWSTR)                // 5120
#define SB_EL (NT * ROWSTR)                // 3840
#define OFF_AH 0
#define OFF_AL (SA_EL)
#define OFF_BH (2 * SA_EL)
#define OFF_BL (2 * SA_EL + SB_EL)
#define STAGE_EL (2 * SA_EL + 2 * SB_EL)   // 17920 elems
#define SMEM_BYTES (2 * STAGE_EL * 2)      // 71680 B -> 3 CTAs/SM

// ---------------- device scratch ----------------
__device__ int   g_cnt[NEXP];
__device__ int   g_tok[NEXP * T_TOK];
__device__ float g_wt [NEXP * T_TOK];
__device__ int   g_nslots[T_TOK];
__device__ int   g_slots[T_TOK * KSEL];
__device__ __nv_bfloat16 g_xh[(size_t)T_TOK * HDIM];
__device__ __nv_bfloat16 g_xl[(size_t)T_TOK * HDIM];
__device__ __nv_bfloat16 g_hh[(size_t)NEXP * T_TOK * IDIM];
__device__ __nv_bfloat16 g_hl[(size_t)NEXP * T_TOK * IDIM];
__device__ float g_o[(size_t)NEXP * T_TOK * HDIM];

// ---------------- helpers ----------------
__device__ __forceinline__ uint32_t smem_u32(const void* p) {
    uint32_t a;
    asm("{ .reg .u64 t; cvta.to.shared.u64 t, %1; cvt.u32.u64 %0, t; }" : "=r"(a) : "l"(p));
    return a;
}
__device__ __forceinline__ void mma_bf16(float* c, const uint32_t* a, const uint32_t* b) {
    asm volatile(
        "mma.sync.aligned.m16n8k16.row.col.f32.bf16.bf16.f32 "
        "{%0,%1,%2,%3}, {%4,%5,%6,%7}, {%8,%9}, {%0,%1,%2,%3};"
        : "+f"(c[0]), "+f"(c[1]), "+f"(c[2]), "+f"(c[3])
        : "r"(a[0]), "r"(a[1]), "r"(a[2]), "r"(a[3]), "r"(b[0]), "r"(b[1]));
}
__device__ __forceinline__ void ldm_x4(uint32_t* r, uint32_t addr) {
    asm volatile("ldmatrix.sync.aligned.m8n8.x4.shared.b16 {%0,%1,%2,%3}, [%4];"
                 : "=r"(r[0]), "=r"(r[1]), "=r"(r[2]), "=r"(r[3]) : "r"(addr));
}
__device__ __forceinline__ void cp16(uint32_t dst, const void* src) {
    asm volatile("cp.async.cg.shared.global [%0], [%1], 16;" :: "r"(dst), "l"(src) : "memory");
}
#define CP_COMMIT() asm volatile("cp.async.commit_group;" ::: "memory")
#define CP_WAIT0()  asm volatile("cp.async.wait_group 0;" ::: "memory")

union U4 { unsigned short s[4]; uint2 q; };
__device__ __forceinline__ void cvt4(const float* v, uint2& hiq, uint2& loq) {
    U4 h, l;
#pragma unroll
    for (int i = 0; i < 4; i++) {
        __nv_bfloat16 bh = __float2bfloat16(v[i]);
        float r = v[i] - __bfloat162float(bh);
        __nv_bfloat16 bl = __float2bfloat16(r);
        h.s[i] = *(unsigned short*)&bh;
        l.s[i] = *(unsigned short*)&bl;
    }
    hiq = h.q; loq = l.q;
}

// ---------------- routing / split kernels ----------------
__global__ void zero_kernel() {
    int i = threadIdx.x;
    if (i < NEXP) g_cnt[i] = 0;
}
__global__ void build_kernel(const int* __restrict__ ridx,
                             const float* __restrict__ rw) {
    int t = blockIdx.x * blockDim.x + threadIdx.x;
    if (t >= T_TOK) return;
    int id[KSEL];
#pragma unroll
    for (int k = 0; k < KSEL; k++) id[k] = ridx[t * KSEL + k];
    int ns = 0;
#pragma unroll
    for (int k = 0; k < KSEL; k++) {
        bool first = true;
#pragma unroll
        for (int j = 0; j < KSEL; j++)
            if (j < k && id[j] == id[k]) first = false;
        if (!first) continue;
        int c = 0;
#pragma unroll
        for (int j = 0; j < KSEL; j++)
            if (id[j] == id[k]) c++;
        int e = id[k];
        float w = rw[t * NEXP + e] * (float)c;
        int loc = atomicAdd(&g_cnt[e], 1);
        g_tok[e * T_TOK + loc] = t;
        g_wt [e * T_TOK + loc] = w;
        g_slots[t * KSEL + ns] = e * T_TOK + loc;
        ns++;
    }
    g_nslots[t] = ns;
}
__global__ void split_x_kernel(const float* __restrict__ x) {
    int i = blockIdx.x * blockDim.x + threadIdx.x;   // float4 index
    if (i >= (T_TOK * HDIM) / 4) return;
    float4 v = ((const float4*)x)[i];
    float a[4] = {v.x, v.y, v.z, v.w};
    uint2 h, l;
    cvt4(a, h, l);
    ((uint2*)g_xh)[i] = h;
    ((uint2*)g_xl)[i] = l;
}

// ---------------- GEMM: MODE 0 = gate_up+GLU -> g_hh/g_hl, MODE 1 = down+scale -> g_o ----
// 128 threads, CTA tile 128x96, warp tile 64x48, 3 CTAs/SM.
// Crossbar-lean: 64-row warp tiles amortize B fragments over 4 m-tiles,
// A fragments over 6 n-tiles -> ~100 B of ldmatrix traffic per MMA (was 142).
template <int MODE>
__global__ __launch_bounds__(128, 3)
void moe_mma_kernel(const float* __restrict__ Bw,
                    const float* __restrict__ bias) {
    constexpr int LDB = (MODE == 0) ? TWO_I : HDIM;
    extern __shared__ __nv_bfloat16 smem[];
    uint32_t sb = smem_u32(smem);

    int e   = blockIdx.z;
    int cnt = g_cnt[e];
    int m0  = blockIdx.x * MT;
    if (m0 >= cnt) return;
    int n0  = blockIdx.y * NT;

    int tid  = threadIdx.x;
    int lane = tid & 31, wid = tid >> 5;    // wid 0..3
    int wm = wid >> 1, wn = wid & 1;        // warp tile: 64 rows x 48 cols

    // ---- A cp.async mapping: one row per thread (128 rows), 4+4 cp16 ----
    int arow_i = tid;                       // 0..127
    const __nv_bfloat16 *ah_src, *al_src;
    {
        int gm = m0 + arow_i;
        if (gm >= cnt) gm = cnt - 1;        // clamp: garbage rows discarded in epilogue
        if (MODE == 0) {
            size_t rb = (size_t)g_tok[e * T_TOK + gm] * HDIM;
            ah_src = g_xh + rb; al_src = g_xl + rb;
        } else {
            size_t rb = ((size_t)e * T_TOK + gm) * IDIM;
            ah_src = g_hh + rb; al_src = g_hl + rb;
        }
    }
    const float* Be = Bw + (size_t)e * HDIM * LDB + n0;

    auto issueA = [&](int c, int s) {
        uint32_t dstA = sb + (s * STAGE_EL + arow_i * ROWSTR) * 2;
        const __nv_bfloat16* sh = ah_src + c * KC;
        const __nv_bfloat16* sl = al_src + c * KC;
#pragma unroll
        for (int g = 0; g < 4; g++) {
            cp16(dstA + OFF_AH * 2 + g * 16, sh + g * 8);
            cp16(dstA + OFF_AL * 2 + g * 16, sl + g * 8);
        }
        CP_COMMIT();
    };

    // ---- B: half h covers k rows [h*16, h*16+16); 12 units of (32 cols x 4 k) ----
    float bv[3][4];
    auto loadB = [&](int c, int h) {
#pragma unroll
        for (int it = 0; it < 3; it++) {
            int unit = wid + it * 4;                 // 0..11
            int col = (unit % 3) * 32 + lane;
            int kb  = h * 16 + (unit / 3) * 4;
            const float* p = Be + (size_t)(c * KC + kb) * LDB + col;
#pragma unroll
            for (int j = 0; j < 4; j++) bv[it][j] = p[(size_t)j * LDB];
        }
    };
    auto storeB = [&](int s, int h) {
        __nv_bfloat16* base = smem + s * STAGE_EL;
#pragma unroll
        for (int it = 0; it < 3; it++) {
            int unit = wid + it * 4;
            int col = (unit % 3) * 32 + lane;
            int kb  = h * 16 + (unit / 3) * 4;
            uint2 hq, lq; cvt4(bv[it], hq, lq);
            __nv_bfloat16* pb = base + col * ROWSTR + kb;
            *(uint2*)(pb + OFF_BH) = hq;
            *(uint2*)(pb + OFF_BL) = lq;
        }
    };

    float acc[4][6][4];
#pragma unroll
    for (int mi = 0; mi < 4; mi++)
#pragma unroll
        for (int ni = 0; ni < 6; ni++)
#pragma unroll
            for (int u = 0; u < 4; u++) acc[mi][ni][u] = 0.f;

    // ldmatrix lane offsets (elems)
    int a_lo = ((lane & 7) + ((lane >> 3) & 1) * 8) * ROWSTR + ((lane >> 4) & 1) * 8;
    int b_lo = ((lane & 7) + ((lane >> 4) & 1) * 8) * ROWSTR + ((lane >> 3) & 1) * 8;

    // A-fragment registers shared across hi/lo passes:
    //   load Ah -> pass1 Ah*Bh, pass2 Ah*Bl -> reload regs with Al -> pass3 Al*Bh
    auto do_ks = [&](int cur, int ks) {
        uint32_t sAh = sb + (cur * STAGE_EL + OFF_AH) * 2;
        uint32_t sAl = sb + (cur * STAGE_EL + OFF_AL) * 2;
        uint32_t sBh = sb + (cur * STAGE_EL + OFF_BH) * 2;
        uint32_t sBl = sb + (cur * STAGE_EL + OFF_BL) * 2;
        uint32_t af[4][4], bh[3][4], bl[3][4];
#pragma unroll
        for (int mi = 0; mi < 4; mi++) {
            uint32_t off = ((wm * 64 + mi * 16) * ROWSTR + ks * 16 + a_lo) * 2;
            ldm_x4(af[mi], sAh + off);
        }
#pragma unroll
        for (int nh = 0; nh < 3; nh++) {
            uint32_t off = ((wn * 48 + nh * 16) * ROWSTR + ks * 16 + b_lo) * 2;
            ldm_x4(bh[nh], sBh + off);
            ldm_x4(bl[nh], sBl + off);
        }
        // pass 1: Ah * Bh (24 independent MMAs)
#pragma unroll
        for (int mi = 0; mi < 4; mi++)
#pragma unroll
            for (int ni = 0; ni < 6; ni++)
                mma_bf16(acc[mi][ni], af[mi], &bh[ni >> 1][(ni & 1) * 2]);
        // pass 2: Ah * Bl
#pragma unroll
        for (int mi = 0; mi < 4; mi++)
#pragma unroll
            for (int ni = 0; ni < 6; ni++)
                mma_bf16(acc[mi][ni], af[mi], &bl[ni >> 1][(ni & 1) * 2]);
        // reload af <- Al, then pass 3: Al * Bh
#pragma unroll
        for (int mi = 0; mi < 4; mi++) {
            uint32_t off = ((wm * 64 + mi * 16) * ROWSTR + ks * 16 + a_lo) * 2;
            ldm_x4(af[mi], sAl + off);
        }
#pragma unroll
        for (int mi = 0; mi < 4; mi++)
#pragma unroll
            for (int ni = 0; ni < 6; ni++)
                mma_bf16(acc[mi][ni], af[mi], &bh[ni >> 1][(ni & 1) * 2]);
    };

    // ---- prologue ----
    issueA(0, 0);
    loadB(0, 0); storeB(0, 0);
    loadB(0, 1); storeB(0, 1);
    CP_WAIT0();
    __syncthreads();

#pragma unroll 1
    for (int c = 0; c < NCHUNK; c++) {
        int cur = c & 1;
        int nxt = cur ^ 1;
        bool more = (c + 1 < NCHUNK);
        if (more) { issueA(c + 1, nxt); loadB(c + 1, 0); }

        do_ks(cur, 0);

        if (more) { storeB(nxt, 0); loadB(c + 1, 1); }

        do_ks(cur, 1);

        if (more) storeB(nxt, 1);
        CP_WAIT0();
        __syncthreads();
    }

    // ---- epilogue ----
    int r = lane >> 2, q = lane & 3;
#pragma unroll
    for (int mi = 0; mi < 4; mi++) {
        int mbase = m0 + wm * 64 + mi * 16 + r;
#pragma unroll
        for (int ni = 0; ni < 6; ni++) {
            int ncol = n0 + wn * 48 + ni * 8 + q * 2;
            if (MODE == 0) {
                float bg = bias[(size_t)e * TWO_I + ncol];
                float bu = bias[(size_t)e * TWO_I + ncol + 1];
                int hcol = ncol >> 1;
#pragma unroll
                for (int h2 = 0; h2 < 2; h2++) {
                    int m = mbase + h2 * 8;
                    if (m < cnt) {
                        float gate = fminf(acc[mi][ni][h2 * 2 + 0] + bg, LIMIT);
                        float up   = fminf(fmaxf(acc[mi][ni][h2 * 2 + 1] + bu, -LIMIT), LIMIT);
                        float glu  = gate / (1.0f + expf(-ALPHA * gate));
                        float h    = (up + 1.0f) * glu;
                        __nv_bfloat16 bh16 = __float2bfloat16(h);
                        float res = h - __bfloat162float(bh16);
                        __nv_bfloat16 bl16 = __float2bfloat16(res);
                        size_t idx = ((size_t)e * T_TOK + m) * IDIM + hcol;
                        g_hh[idx] = bh16;
                        g_hl[idx] = bl16;
                    }
                }
            } else {
                float b0v = bias[(size_t)e * HDIM + ncol];
                float b1v = bias[(size_t)e * HDIM + ncol + 1];
#pragma unroll
                for (int h2 = 0; h2 < 2; h2++) {
                    int m = mbase + h2 * 8;
                    if (m < cnt) {
                        float w = g_wt[e * T_TOK + m];
                        float2 v;
                        v.x = (acc[mi][ni][h2 * 2 + 0] + b0v) * w;
                        v.y = (acc[mi][ni][h2 * 2 + 1] + b1v) * w;
                        *(float2*)&g_o[((size_t)e * T_TOK + m) * HDIM + ncol] = v;
                    }
                }
            }
        }
    }
}

// ---------------- deterministic per-token combine ----------------
__global__ void combine_kernel(float* __restrict__ out) {
    int t = blockIdx.x;
    int ns = g_nslots[t];
    int sl[KSEL];
#pragma unroll
    for (int j = 0; j < KSEL; j++)
        sl[j] = (j < ns) ? g_slots[t * KSEL + j] : -1;

    for (int c = threadIdx.x * 4; c < HDIM; c += blockDim.x * 4) {
        float4 acc = make_float4(0.f, 0.f, 0.f, 0.f);
#pragma unroll
        for (int j = 0; j < KSEL; j++) {
            if (sl[j] < 0) continue;
            float4 v = *(const float4*)&g_o[(size_t)sl[j] * HDIM + c];
            acc.x += v.x; acc.y += v.y; acc.z += v.z; acc.w += v.w;
        }
        *(float4*)&out[(size_t)t * HDIM + c] = acc;
    }
}

// ---------------- launch ----------------
extern "C" void kernel_launch(void* const* d_in, const int* in_sizes, int n_in,
                              void* d_out, int out_size) {
    const float* x    = (const float*)d_in[0];
    const int*   ridx = (const int*)  d_in[1];
    const float* rw   = (const float*)d_in[2];
    const float* w1   = (const float*)d_in[3];
    const float* b1   = (const float*)d_in[4];
    const float* w2   = (const float*)d_in[5];
    const float* b2   = (const float*)d_in[6];
    float* out = (float*)d_out;

    cudaFuncSetAttribute(moe_mma_kernel<0>,
                         cudaFuncAttributeMaxDynamicSharedMemorySize, SMEM_BYTES);
    cudaFuncSetAttribute(moe_mma_kernel<1>,
                         cudaFuncAttributeMaxDynamicSharedMemorySize, SMEM_BYTES);

    zero_kernel<<<1, 32>>>();
    build_kernel<<<(T_TOK + 255) / 256, 256>>>(ridx, rw);
    split_x_kernel<<<(T_TOK * HDIM / 4 + 255) / 256, 256>>>(x);

    // blockIdx.x = M tile (4), blockIdx.y = N tile, blockIdx.z = expert
    dim3 g1((T_TOK + MT - 1) / MT, TWO_I / NT, NEXP);  // (4, 60, 8)
    moe_mma_kernel<0><<<g1, 128, SMEM_BYTES>>>(w1, b1);

    dim3 g2((T_TOK + MT - 1) / MT, HDIM / NT, NEXP);   // (4, 30, 8)
    moe_mma_kernel<1><<<g2, 128, SMEM_BYTES>>>(w2, b2);

    combine_kernel<<<T_TOK, 256>>>(out);
}

// round 17
// speedup vs baseline: 1.5878x; 1.5878x over previous
#include <cuda_runtime.h>
#include <cuda_bf16.h>
#include <cstdint>
#include <math.h>

// ---------------- problem constants ----------------
#define T_TOK 512
#define HDIM 2880
#define IDIM 2880
#define TWO_I 5760
#define NEXP 8
#define KSEL 4
#define ALPHA 1.702f
#define LIMIT 7.0f

// ---------------- GEMM tiling ----------------
#define MT 64
#define NT 96
#define KC 32
#define NCHUNK (HDIM / KC)     // 90
#define ROWSTR 40              // smem row stride (32 data + 8 pad) bf16 elems

#define SA_EL (MT * ROWSTR)                // 2560
#define SB_EL (NT * ROWSTR)                // 3840
#define OFF_AH 0
#define OFF_AL (SA_EL)
#define OFF_BH (2 * SA_EL)
#define OFF_BL (2 * SA_EL + SB_EL)
#define STAGE_EL (2 * SA_EL + 2 * SB_EL)   // 12800 elems
#define SMEM_BYTES (2 * STAGE_EL * 2)      // 51200 B -> 4 CTAs/SM

// ---------------- device scratch ----------------
__device__ int   g_cnt[NEXP];
__device__ int   g_tok[NEXP * T_TOK];
__device__ float g_wt [NEXP * T_TOK];
__device__ int   g_nslots[T_TOK];
__device__ int   g_slots[T_TOK * KSEL];
__device__ __nv_bfloat16 g_xh[(size_t)T_TOK * HDIM];
__device__ __nv_bfloat16 g_xl[(size_t)T_TOK * HDIM];
__device__ __nv_bfloat16 g_hh[(size_t)NEXP * T_TOK * IDIM];
__device__ __nv_bfloat16 g_hl[(size_t)NEXP * T_TOK * IDIM];
__device__ float g_o[(size_t)NEXP * T_TOK * HDIM];

// ---------------- helpers ----------------
__device__ __forceinline__ uint32_t smem_u32(const void* p) {
    uint32_t a;
    asm("{ .reg .u64 t; cvta.to.shared.u64 t, %1; cvt.u32.u64 %0, t; }" : "=r"(a) : "l"(p));
    return a;
}
__device__ __forceinline__ void mma_bf16(float* c, const uint32_t* a, const uint32_t* b) {
    asm volatile(
        "mma.sync.aligned.m16n8k16.row.col.f32.bf16.bf16.f32 "
        "{%0,%1,%2,%3}, {%4,%5,%6,%7}, {%8,%9}, {%0,%1,%2,%3};"
        : "+f"(c[0]), "+f"(c[1]), "+f"(c[2]), "+f"(c[3])
        : "r"(a[0]), "r"(a[1]), "r"(a[2]), "r"(a[3]), "r"(b[0]), "r"(b[1]));
}
__device__ __forceinline__ void ldm_x4(uint32_t* r, uint32_t addr) {
    asm volatile("ldmatrix.sync.aligned.m8n8.x4.shared.b16 {%0,%1,%2,%3}, [%4];"
                 : "=r"(r[0]), "=r"(r[1]), "=r"(r[2]), "=r"(r[3]) : "r"(addr));
}
__device__ __forceinline__ void cp16(uint32_t dst, const void* src) {
    asm volatile("cp.async.cg.shared.global [%0], [%1], 16;" :: "r"(dst), "l"(src) : "memory");
}
#define CP_COMMIT() asm volatile("cp.async.commit_group;" ::: "memory")
#define CP_WAIT0()  asm volatile("cp.async.wait_group 0;" ::: "memory")

union U4 { unsigned short s[4]; uint2 q; };
__device__ __forceinline__ void cvt4(const float* v, uint2& hiq, uint2& loq) {
    U4 h, l;
#pragma unroll
    for (int i = 0; i < 4; i++) {
        __nv_bfloat16 bh = __float2bfloat16(v[i]);
        float r = v[i] - __bfloat162float(bh);
        __nv_bfloat16 bl = __float2bfloat16(r);
        h.s[i] = *(unsigned short*)&bh;
        l.s[i] = *(unsigned short*)&bl;
    }
    hiq = h.q; loq = l.q;
}

// ---------------- routing / split kernels ----------------
__global__ void zero_kernel() {
    int i = threadIdx.x;
    if (i < NEXP) g_cnt[i] = 0;
}
__global__ void build_kernel(const int* __restrict__ ridx,
                             const float* __restrict__ rw) {
    int t = blockIdx.x * blockDim.x + threadIdx.x;
    if (t >= T_TOK) return;
    int id[KSEL];
#pragma unroll
    for (int k = 0; k < KSEL; k++) id[k] = ridx[t * KSEL + k];
    int ns = 0;
#pragma unroll
    for (int k = 0; k < KSEL; k++) {
        bool first = true;
#pragma unroll
        for (int j = 0; j < KSEL; j++)
            if (j < k && id[j] == id[k]) first = false;
        if (!first) continue;
        int c = 0;
#pragma unroll
        for (int j = 0; j < KSEL; j++)
            if (id[j] == id[k]) c++;
        int e = id[k];
        float w = rw[t * NEXP + e] * (float)c;
        int loc = atomicAdd(&g_cnt[e], 1);
        g_tok[e * T_TOK + loc] = t;
        g_wt [e * T_TOK + loc] = w;
        g_slots[t * KSEL + ns] = e * T_TOK + loc;
        ns++;
    }
    g_nslots[t] = ns;
}
__global__ void split_x_kernel(const float* __restrict__ x) {
    int i = blockIdx.x * blockDim.x + threadIdx.x;   // float4 index
    if (i >= (T_TOK * HDIM) / 4) return;
    float4 v = ((const float4*)x)[i];
    float a[4] = {v.x, v.y, v.z, v.w};
    uint2 h, l;
    cvt4(a, h, l);
    ((uint2*)g_xh)[i] = h;
    ((uint2*)g_xl)[i] = l;
}

// ---------------- GEMM: MODE 0 = gate_up+GLU -> g_hh/g_hl, MODE 1 = down+scale -> g_o ----
// 128 threads, CTA tile 64x96, warp tile 32x48, 4 CTAs/SM.
// 16-row-granular skipping of padded M sub-tiles in the last partial tile of
// each expert (warp-uniform predicates; valid rows keep identical accumulation).
template <int MODE>
__global__ __launch_bounds__(128, 4)
void moe_mma_kernel(const float* __restrict__ Bw,
                    const float* __restrict__ bias) {
    constexpr int LDB = (MODE == 0) ? TWO_I : HDIM;
    extern __shared__ __nv_bfloat16 smem[];
    uint32_t sb = smem_u32(smem);

    int e   = blockIdx.z;
    int cnt = g_cnt[e];
    int m0  = blockIdx.x * MT;
    if (m0 >= cnt) return;
    int n0  = blockIdx.y * NT;

    int tid  = threadIdx.x;
    int lane = tid & 31, wid = tid >> 5;    // wid 0..3
    int wm = wid >> 1, wn = wid & 1;        // warp tile: 32 rows x 48 cols

    // active-row predicates for this warp's two 16-row sub-tiles
    int act = cnt - m0 - wm * 32;           // rows this warp actually owns
    bool m1a = (act > 0);
    bool m2a = (act > 16);

    // ---- A cp.async mapping: row = tid/2, 16-elem half = (tid&1) ----
    int arow_i = tid >> 1;                  // 0..63
    int aseg   = (tid & 1) * 16;
    const __nv_bfloat16 *ah_src, *al_src;
    {
        int gm = m0 + arow_i;
        if (gm >= cnt) gm = cnt - 1;        // clamp: garbage rows never used for output
        if (MODE == 0) {
            size_t rb = (size_t)g_tok[e * T_TOK + gm] * HDIM;
            ah_src = g_xh + rb; al_src = g_xl + rb;
        } else {
            size_t rb = ((size_t)e * T_TOK + gm) * IDIM;
            ah_src = g_hh + rb; al_src = g_hl + rb;
        }
    }
    const float* Be = Bw + (size_t)e * HDIM * LDB + n0;

    auto issueA = [&](int c, int s) {
        uint32_t dstA = sb + (s * STAGE_EL + arow_i * ROWSTR + aseg) * 2;
        const __nv_bfloat16* sh = ah_src + c * KC + aseg;
        const __nv_bfloat16* sl = al_src + c * KC + aseg;
        cp16(dstA + OFF_AH * 2, sh);
        cp16(dstA + OFF_AH * 2 + 16, sh + 8);
        cp16(dstA + OFF_AL * 2, sl);
        cp16(dstA + OFF_AL * 2 + 16, sl + 8);
        CP_COMMIT();
    };

    // ---- B: half h covers k rows [h*16, h*16+16); 12 units of (32 cols x 4 k) ----
    float bv[2][3][4];
    auto loadB = [&](int c, int h) {
#pragma unroll
        for (int it = 0; it < 3; it++) {
            int unit = wid + it * 4;                 // 0..11
            int col = (unit % 3) * 32 + lane;
            int kb  = h * 16 + (unit / 3) * 4;
            const float* p = Be + (size_t)(c * KC + kb) * LDB + col;
#pragma unroll
            for (int j = 0; j < 4; j++) bv[h][it][j] = p[(size_t)j * LDB];
        }
    };
    auto storeB = [&](int s, int h) {
        __nv_bfloat16* base = smem + s * STAGE_EL;
#pragma unroll
        for (int it = 0; it < 3; it++) {
            int unit = wid + it * 4;
            int col = (unit % 3) * 32 + lane;
            int kb  = h * 16 + (unit / 3) * 4;
            uint2 hq, lq; cvt4(bv[h][it], hq, lq);
            __nv_bfloat16* pb = base + col * ROWSTR + kb;
            *(uint2*)(pb + OFF_BH) = hq;
            *(uint2*)(pb + OFF_BL) = lq;
        }
    };

    float acc[2][6][4];
#pragma unroll
    for (int mi = 0; mi < 2; mi++)
#pragma unroll
        for (int ni = 0; ni < 6; ni++)
#pragma unroll
            for (int u = 0; u < 4; u++) acc[mi][ni][u] = 0.f;

    // ldmatrix lane offsets (elems)
    int a_lo = ((lane & 7) + ((lane >> 3) & 1) * 8) * ROWSTR + ((lane >> 4) & 1) * 8;
    int b_lo = ((lane & 7) + ((lane >> 4) & 1) * 8) * ROWSTR + ((lane >> 3) & 1) * 8;

    // A-fragment registers shared across hi/lo passes:
    //   load Ah -> pass1 Ah*Bh, pass2 Ah*Bl -> reload regs with Al -> pass3 Al*Bh
    // Sub-tile mi executes only if mi*16 < act (warp-uniform).
    auto do_ks = [&](int cur, int ks) {
        if (!m1a) return;                    // whole warp beyond cnt: no MMA work
        uint32_t sAh = sb + (cur * STAGE_EL + OFF_AH) * 2;
        uint32_t sAl = sb + (cur * STAGE_EL + OFF_AL) * 2;
        uint32_t sBh = sb + (cur * STAGE_EL + OFF_BH) * 2;
        uint32_t sBl = sb + (cur * STAGE_EL + OFF_BL) * 2;
        uint32_t af[2][4], bh[3][4], bl[3][4];
        {
            uint32_t off0 = ((wm * 32 + 0) * ROWSTR + ks * 16 + a_lo) * 2;
            ldm_x4(af[0], sAh + off0);
            if (m2a) {
                uint32_t off1 = ((wm * 32 + 16) * ROWSTR + ks * 16 + a_lo) * 2;
                ldm_x4(af[1], sAh + off1);
            }
        }
#pragma unroll
        for (int nh = 0; nh < 3; nh++) {
            uint32_t off = ((wn * 48 + nh * 16) * ROWSTR + ks * 16 + b_lo) * 2;
            ldm_x4(bh[nh], sBh + off);
            ldm_x4(bl[nh], sBl + off);
        }
        // pass 1: Ah * Bh
#pragma unroll
        for (int ni = 0; ni < 6; ni++)
            mma_bf16(acc[0][ni], af[0], &bh[ni >> 1][(ni & 1) * 2]);
        if (m2a) {
#pragma unroll
            for (int ni = 0; ni < 6; ni++)
                mma_bf16(acc[1][ni], af[1], &bh[ni >> 1][(ni & 1) * 2]);
        }
        // pass 2: Ah * Bl
#pragma unroll
        for (int ni = 0; ni < 6; ni++)
            mma_bf16(acc[0][ni], af[0], &bl[ni >> 1][(ni & 1) * 2]);
        if (m2a) {
#pragma unroll
            for (int ni = 0; ni < 6; ni++)
                mma_bf16(acc[1][ni], af[1], &bl[ni >> 1][(ni & 1) * 2]);
        }
        // reload af <- Al, then pass 3: Al * Bh
        {
            uint32_t off0 = ((wm * 32 + 0) * ROWSTR + ks * 16 + a_lo) * 2;
            ldm_x4(af[0], sAl + off0);
            if (m2a) {
                uint32_t off1 = ((wm * 32 + 16) * ROWSTR + ks * 16 + a_lo) * 2;
                ldm_x4(af[1], sAl + off1);
            }
        }
#pragma unroll
        for (int ni = 0; ni < 6; ni++)
            mma_bf16(acc[0][ni], af[0], &bh[ni >> 1][(ni & 1) * 2]);
        if (m2a) {
#pragma unroll
            for (int ni = 0; ni < 6; ni++)
                mma_bf16(acc[1][ni], af[1], &bh[ni >> 1][(ni & 1) * 2]);
        }
    };

    // ---- prologue ----
    issueA(0, 0);
    loadB(0, 0); loadB(0, 1);
    storeB(0, 0); storeB(0, 1);
    CP_WAIT0();
    __syncthreads();

#pragma unroll 1
    for (int c = 0; c < NCHUNK; c++) {
        int cur = c & 1;
        int nxt = cur ^ 1;
        bool more = (c + 1 < NCHUNK);
        if (more) {
            issueA(c + 1, nxt);
            loadB(c + 1, 0);
            loadB(c + 1, 1);
        }

        do_ks(cur, 0);
        do_ks(cur, 1);

        if (more) {
            storeB(nxt, 0);
            storeB(nxt, 1);
        }
        CP_WAIT0();
        __syncthreads();
    }

    // ---- epilogue ----
    int r = lane >> 2, q = lane & 3;
#pragma unroll
    for (int mi = 0; mi < 2; mi++) {
        int mbase = m0 + wm * 32 + mi * 16 + r;
#pragma unroll
        for (int ni = 0; ni < 6; ni++) {
            int ncol = n0 + wn * 48 + ni * 8 + q * 2;
            if (MODE == 0) {
                float bg = bias[(size_t)e * TWO_I + ncol];
                float bu = bias[(size_t)e * TWO_I + ncol + 1];
                int hcol = ncol >> 1;
#pragma unroll
                for (int h2 = 0; h2 < 2; h2++) {
                    int m = mbase + h2 * 8;
                    if (m < cnt) {
                        float gate = fminf(acc[mi][ni][h2 * 2 + 0] + bg, LIMIT);
                        float up   = fminf(fmaxf(acc[mi][ni][h2 * 2 + 1] + bu, -LIMIT), LIMIT);
                        float glu  = gate / (1.0f + expf(-ALPHA * gate));
                        float h    = (up + 1.0f) * glu;
                        __nv_bfloat16 bh16 = __float2bfloat16(h);
                        float res = h - __bfloat162float(bh16);
                        __nv_bfloat16 bl16 = __float2bfloat16(res);
                        size_t idx = ((size_t)e * T_TOK + m) * IDIM + hcol;
                        g_hh[idx] = bh16;
                        g_hl[idx] = bl16;
                    }
                }
            } else {
                float b0v = bias[(size_t)e * HDIM + ncol];
                float b1v = bias[(size_t)e * HDIM + ncol + 1];
#pragma unroll
                for (int h2 = 0; h2 < 2; h2++) {
                    int m = mbase + h2 * 8;
                    if (m < cnt) {
                        float w = g_wt[e * T_TOK + m];
                        float2 v;
                        v.x = (acc[mi][ni][h2 * 2 + 0] + b0v) * w;
                        v.y = (acc[mi][ni][h2 * 2 + 1] + b1v) * w;
                        *(float2*)&g_o[((size_t)e * T_TOK + m) * HDIM + ncol] = v;
                    }
                }
            }
        }
    }
}

// ---------------- deterministic per-token combine ----------------
__global__ void combine_kernel(float* __restrict__ out) {
    int t = blockIdx.x;
    int ns = g_nslots[t];
    int sl[KSEL];
#pragma unroll
    for (int j = 0; j < KSEL; j++)
        sl[j] = (j < ns) ? g_slots[t * KSEL + j] : -1;

    for (int c = threadIdx.x * 4; c < HDIM; c += blockDim.x * 4) {
        float4 acc = make_float4(0.f, 0.f, 0.f, 0.f);
#pragma unroll
        for (int j = 0; j < KSEL; j++) {
            if (sl[j] < 0) continue;
            float4 v = *(const float4*)&g_o[(size_t)sl[j] * HDIM + c];
            acc.x += v.x; acc.y += v.y; acc.z += v.z; acc.w += v.w;
        }
        *(float4*)&out[(size_t)t * HDIM + c] = acc;
    }
}

// ---------------- launch ----------------
extern "C" void kernel_launch(void* const* d_in, const int* in_sizes, int n_in,
                              void* d_out, int out_size) {
    const float* x    = (const float*)d_in[0];
    const int*   ridx = (const int*)  d_in[1];
    const float* rw   = (const float*)d_in[2];
    const float* w1   = (const float*)d_in[3];
    const float* b1   = (const float*)d_in[4];
    const float* w2   = (const float*)d_in[5];
    const float* b2   = (const float*)d_in[6];
    float* out = (float*)d_out;

    cudaFuncSetAttribute(moe_mma_kernel<0>,
                         cudaFuncAttributeMaxDynamicSharedMemorySize, SMEM_BYTES);
    cudaFuncSetAttribute(moe_mma_kernel<1>,
                         cudaFuncAttributeMaxDynamicSharedMemorySize, SMEM_BYTES);

    zero_kernel<<<1, 32>>>();
    build_kernel<<<(T_TOK + 255) / 256, 256>>>(ridx, rw);
    split_x_kernel<<<(T_TOK * HDIM / 4 + 255) / 256, 256>>>(x);

    // blockIdx.x = M tile (8), blockIdx.y = N tile, blockIdx.z = expert
    dim3 g1((T_TOK + MT - 1) / MT, TWO_I / NT, NEXP);  // (8, 60, 8)
    moe_mma_kernel<0><<<g1, 128, SMEM_BYTES>>>(w1, b1);

    dim3 g2((T_TOK + MT - 1) / MT, HDIM / NT, NEXP);   // (8, 30, 8)
    moe_mma_kernel<1><<<g2, 128, SMEM_BYTES>>>(w2, b2);

    combine_kernel<<<T_TOK, 256>>>(out);
}